// round 13
// baseline (speedup 1.0000x reference)
#include <cuda_runtime.h>
#include <cuda_bf16.h>
#include <math.h>
#include <stdint.h>

#define NN   16384
#define NE   8192
#define CD   256
#define NNZP 262144
#define ATT_SCALE 0.17677669529663687f  /* 1/sqrt(32) */
#define LOG2E 1.4426950408889634f

// ---------------- scratch (device globals; no allocation allowed) ----------------
__device__ float g_Q[NN * CD];
__device__ float g_K[NN * CD];
__device__ float g_V[NN * CD];
__device__ float g_Xnode[NN * CD];
__device__ float g_Oacc[NN * CD];
__device__ __nv_bfloat16 g_Qb[NN * CD];
__device__ __nv_bfloat16 g_Keb[NE * CD];
__device__ __nv_bfloat16 g_XeT[CD * NE];
__device__ __nv_bfloat16 g_Xh[NN * CD];
__device__ __nv_bfloat16 g_Xl[NN * CD];
__device__ __nv_bfloat16 g_Xeh[NE * CD];
__device__ __nv_bfloat16 g_WtH[4][CD * CD];
__device__ __nv_bfloat16 g_WtL[4][CD * CD];
__device__ int g_hist[NE];
__device__ int g_off[NE + 1];
__device__ int g_cur[NE];
__device__ int g_idx[NNZP];

// ================= PTX helpers =================
__device__ __forceinline__ uint32_t smem_u32(const void* p) {
    uint32_t a;
    asm("{ .reg .u64 t; cvta.to.shared.u64 t, %1; cvt.u32.u64 %0, t; }" : "=r"(a) : "l"(p));
    return a;
}
#define CP16(dst, src)   asm volatile("cp.async.cg.shared.global [%0], [%1], 16;" :: "r"(dst), "l"(src) : "memory")
#define CP_COMMIT()      asm volatile("cp.async.commit_group;" ::: "memory")
#define CP_WAIT0()       asm volatile("cp.async.wait_group 0;" ::: "memory")
#define CP_WAIT1()       asm volatile("cp.async.wait_group 1;" ::: "memory")
#define BAR64(id)        asm volatile("bar.sync %0, 64;" :: "r"(id) : "memory")

#define LDSM4(r0, r1, r2, r3, addr) \
    asm volatile("ldmatrix.sync.aligned.m8n8.x4.shared.b16 {%0,%1,%2,%3}, [%4];" \
                 : "=r"(r0), "=r"(r1), "=r"(r2), "=r"(r3) : "r"(addr))

#define MMA16816(d, a0, a1, a2, a3, b0, b1) \
    asm volatile("mma.sync.aligned.m16n8k16.row.col.f32.bf16.bf16.f32 " \
                 "{%0,%1,%2,%3}, {%4,%5,%6,%7}, {%8,%9}, {%0,%1,%2,%3};" \
                 : "+f"((d)[0]), "+f"((d)[1]), "+f"((d)[2]), "+f"((d)[3]) \
                 : "r"(a0), "r"(a1), "r"(a2), "r"(a3), "r"(b0), "r"(b1))

__device__ __forceinline__ uint32_t packbf(float x, float y) {
    __nv_bfloat162 h = __float22bfloat162_rn(make_float2(x, y));
    return *(uint32_t*)&h;
}
__device__ __forceinline__ float ex2f(float x) {
    float y;
    asm("ex2.approx.ftz.f32 %0, %1;" : "=f"(y) : "f"(x));
    return y;
}

// ================= CSR build + gather aggregation =================
__global__ __launch_bounds__(256) void k_zi() {
    int i = blockIdx.x * 256 + threadIdx.x;
    g_hist[i] = 0;
}
__global__ __launch_bounds__(256) void k_hist(const int* __restrict__ e_ids) {
    int i = blockIdx.x * 256 + threadIdx.x;
    atomicAdd(&g_hist[e_ids[i]], 1);
}
__global__ __launch_bounds__(1024) void k_scan() {
    __shared__ int ws[32];
    int tid = threadIdx.x;
    int lane = tid & 31, w = tid >> 5;
    int base = tid * 8;
    int v[8];
    int s = 0;
#pragma unroll
    for (int i = 0; i < 8; i++) { v[i] = g_hist[base + i]; s += v[i]; }
    int pre = s;
#pragma unroll
    for (int off = 1; off < 32; off <<= 1) {
        int n = __shfl_up_sync(0xffffffff, pre, off);
        if (lane >= off) pre += n;
    }
    if (lane == 31) ws[w] = pre;
    __syncthreads();
    if (w == 0) {
        int t = ws[lane];
#pragma unroll
        for (int off = 1; off < 32; off <<= 1) {
            int n = __shfl_up_sync(0xffffffff, t, off);
            if (lane >= off) t += n;
        }
        ws[lane] = t;
    }
    __syncthreads();
    int excl = (w > 0 ? ws[w - 1] : 0) + (pre - s);
#pragma unroll
    for (int i = 0; i < 8; i++) {
        g_off[base + i] = excl;
        g_cur[base + i] = excl;
        excl += v[i];
    }
    if (tid == 1023) g_off[NE] = NNZP;
}
__global__ __launch_bounds__(256) void k_fill(const int* __restrict__ v_ids,
                                              const int* __restrict__ e_ids) {
    int i = blockIdx.x * 256 + threadIdx.x;
    int e = e_ids[i];
    int pos = atomicAdd(&g_cur[e], 1);
    g_idx[pos] = v_ids[i];
}
__global__ __launch_bounds__(256) void k_gather(const float* __restrict__ X) {
    int e = blockIdx.x;
    int tid = threadIdx.x;
    int j0 = g_off[e], j1 = g_off[e + 1];
    float acc = 0.0f;
    int j = j0;
    for (; j + 4 <= j1; j += 4) {
        int v0 = __ldg(&g_idx[j]);
        int v1 = __ldg(&g_idx[j + 1]);
        int v2 = __ldg(&g_idx[j + 2]);
        int v3 = __ldg(&g_idx[j + 3]);
        acc += __ldg(&X[(size_t)v0 * CD + tid]);
        acc += __ldg(&X[(size_t)v1 * CD + tid]);
        acc += __ldg(&X[(size_t)v2 * CD + tid]);
        acc += __ldg(&X[(size_t)v3 * CD + tid]);
    }
    for (; j < j1; j++)
        acc += __ldg(&X[(size_t)__ldg(&g_idx[j]) * CD + tid]);
    float mean = acc / fmaxf((float)(j1 - j0), 1.0f);
    g_Xeh[(size_t)e * CD + tid] = __float2bfloat16(mean);
}

// ---------------- fp32 -> bf16 hi/lo split ----------------
__global__ __launch_bounds__(256) void k_split(const float* __restrict__ in,
                                               __nv_bfloat16* __restrict__ hi,
                                               __nv_bfloat16* __restrict__ lo) {
    int i = blockIdx.x * 256 + threadIdx.x;
    float4 v = ((const float4*)in)[i];
    __nv_bfloat16 h0 = __float2bfloat16(v.x), h1 = __float2bfloat16(v.y);
    __nv_bfloat16 h2 = __float2bfloat16(v.z), h3 = __float2bfloat16(v.w);
    uint32_t* hp = (uint32_t*)hi;
    uint32_t* lp = (uint32_t*)lo;
    hp[2 * i]     = packbf(__bfloat162float(h0), __bfloat162float(h1));
    hp[2 * i + 1] = packbf(__bfloat162float(h2), __bfloat162float(h3));
    lp[2 * i]     = packbf(v.x - __bfloat162float(h0), v.y - __bfloat162float(h1));
    lp[2 * i + 1] = packbf(v.z - __bfloat162float(h2), v.w - __bfloat162float(h3));
}

// ---------------- W [k][n] -> Wt hi/lo [n][k] bf16 ----------------
__device__ __forceinline__ void split_w_body(const float* __restrict__ W,
                                             __nv_bfloat16* __restrict__ WtH,
                                             __nv_bfloat16* __restrict__ WtL) {
    __shared__ float t[32][33];
    int k0 = blockIdx.x * 32, n0 = blockIdx.y * 32;
    int x = threadIdx.x & 31, y = threadIdx.x >> 5;
#pragma unroll
    for (int i = 0; i < 32; i += 8)
        t[y + i][x] = W[(size_t)(k0 + y + i) * CD + n0 + x];
    __syncthreads();
#pragma unroll
    for (int i = 0; i < 32; i += 8) {
        float w = t[x][y + i];
        __nv_bfloat16 h = __float2bfloat16(w);
        WtH[(size_t)(n0 + y + i) * CD + k0 + x] = h;
        WtL[(size_t)(n0 + y + i) * CD + k0 + x] = __float2bfloat16(w - __bfloat162float(h));
    }
}
__global__ __launch_bounds__(256) void k_split_w(const float* __restrict__ W,
                                                 __nv_bfloat16* __restrict__ WtH,
                                                 __nv_bfloat16* __restrict__ WtL) {
    split_w_body(W, WtH, WtL);
}
__global__ __launch_bounds__(256) void k_split_w3(const float* __restrict__ W0,
                                                  const float* __restrict__ W1,
                                                  const float* __restrict__ W2,
                                                  __nv_bfloat16* __restrict__ WtH,
                                                  __nv_bfloat16* __restrict__ WtL) {
    int z = blockIdx.z;
    const float* W = (z == 0) ? W0 : (z == 1) ? W1 : W2;
    split_w_body(W, WtH + (size_t)z * CD * CD, WtL + (size_t)z * CD * CD);
}

// ================== split-bf16 tensor-core GEMM ==================
#define GLD 72
#define G_AH 0
#define G_AL 18432
#define G_WH 36864
#define G_WL 46080
#define G_STAGE 55296
#define SMEM_GEMM 110592

__device__ __forceinline__ void tgemm_body(
    const __nv_bfloat16* __restrict__ Ah, const __nv_bfloat16* __restrict__ Al,
    const __nv_bfloat16* __restrict__ Wh, const __nv_bfloat16* __restrict__ Wl,
    const float* __restrict__ bias, float* __restrict__ out,
    __nv_bfloat16* __restrict__ out_bf, float bscale, int npasses, char* smg)
{
    const uint32_t sb = smem_u32(smg);
    const int tid = threadIdx.x, wid = tid >> 5, lane = tid & 31;
    const int row0 = blockIdx.x * 128, col0 = blockIdx.y * 64;
    const int wm = wid >> 1, wn = wid & 1;

    const int a_row = lane & 15;
    const int a_koff = (lane >> 4) * 8;
    const int b_row = (lane & 7) + (lane >> 4) * 8;
    const int b_koff = ((lane >> 3) & 1) * 8;

    float acc[2][4][4];
#pragma unroll
    for (int im = 0; im < 2; im++)
#pragma unroll
        for (int nf = 0; nf < 4; nf++)
#pragma unroll
            for (int q = 0; q < 4; q++) acc[im][nf][q] = 0.0f;

    auto load_stage = [&](int kc, int st) {
        uint32_t base = sb + st * G_STAGE;
        const char* ah = (const char*)(Ah + (size_t)row0 * CD + kc * 64);
#pragma unroll
        for (int j = 0; j < 4; j++) {
            int i = tid + j * 256;
            int r = i >> 3, c8 = i & 7;
            CP16(base + G_AH + (r * GLD + c8 * 8) * 2, ah + (r * CD + c8 * 8) * 2);
        }
        const char* wh = (const char*)(Wh + (size_t)col0 * CD + kc * 64);
#pragma unroll
        for (int j = 0; j < 2; j++) {
            int i = tid + j * 256;
            int r = i >> 3, c8 = i & 7;
            CP16(base + G_WH + (r * GLD + c8 * 8) * 2, wh + (r * CD + c8 * 8) * 2);
        }
        if (npasses == 3) {
            const char* al = (const char*)(Al + (size_t)row0 * CD + kc * 64);
#pragma unroll
            for (int j = 0; j < 4; j++) {
                int i = tid + j * 256;
                int r = i >> 3, c8 = i & 7;
                CP16(base + G_AL + (r * GLD + c8 * 8) * 2, al + (r * CD + c8 * 8) * 2);
            }
            const char* wl = (const char*)(Wl + (size_t)col0 * CD + kc * 64);
#pragma unroll
            for (int j = 0; j < 2; j++) {
                int i = tid + j * 256;
                int r = i >> 3, c8 = i & 7;
                CP16(base + G_WL + (r * GLD + c8 * 8) * 2, wl + (r * CD + c8 * 8) * 2);
            }
        }
    };

    load_stage(0, 0);
    CP_COMMIT();

    for (int kc = 0; kc < 4; kc++) {
        if (kc < 3) {
            load_stage(kc + 1, (kc + 1) & 1);
            CP_COMMIT();
            CP_WAIT1();
        } else {
            CP_WAIT0();
        }
        __syncthreads();

        const uint32_t base = sb + (kc & 1) * G_STAGE;
        const uint32_t aoffs[3] = {G_AH, G_AH, G_AL};
        const uint32_t woffs[3] = {G_WH, G_WL, G_WH};
        for (int p = 0; p < npasses; p++) {
            const uint32_t ab = base + aoffs[p];
            const uint32_t wb = base + woffs[p];
#pragma unroll
            for (int kk = 0; kk < 4; kk++) {
                uint32_t a[2][4];
#pragma unroll
                for (int im = 0; im < 2; im++)
                    LDSM4(a[im][0], a[im][1], a[im][2], a[im][3],
                          ab + ((wm * 32 + im * 16 + a_row) * GLD + kk * 16 + a_koff) * 2);
#pragma unroll
                for (int gn = 0; gn < 2; gn++) {
                    uint32_t b0, b1, b2, b3;
                    LDSM4(b0, b1, b2, b3,
                          wb + ((wn * 32 + gn * 16 + b_row) * GLD + kk * 16 + b_koff) * 2);
#pragma unroll
                    for (int im = 0; im < 2; im++) {
                        MMA16816(acc[im][gn * 2],     a[im][0], a[im][1], a[im][2], a[im][3], b0, b1);
                        MMA16816(acc[im][gn * 2 + 1], a[im][0], a[im][1], a[im][2], a[im][3], b2, b3);
                    }
                }
            }
        }
        __syncthreads();
    }

    const int r_base = row0 + wm * 32 + (lane >> 2);
    const int c_base = col0 + wn * 32 + 2 * (lane & 3);
#pragma unroll
    for (int im = 0; im < 2; im++) {
        const int r0 = r_base + im * 16;
        const int r1 = r0 + 8;
#pragma unroll
        for (int nf = 0; nf < 4; nf++) {
            const int c = c_base + nf * 8;
            const float bv0 = __ldg(bias + c), bv1 = __ldg(bias + c + 1);
            float v00 = acc[im][nf][0] + bv0, v01 = acc[im][nf][1] + bv1;
            float v10 = acc[im][nf][2] + bv0, v11 = acc[im][nf][3] + bv1;
            if (out) {
                *(float2*)(out + (size_t)r0 * CD + c) = make_float2(v00, v01);
                *(float2*)(out + (size_t)r1 * CD + c) = make_float2(v10, v11);
            }
            if (out_bf) {
                *(uint32_t*)(out_bf + (size_t)r0 * CD + c) = packbf(v00 * bscale, v01 * bscale);
                *(uint32_t*)(out_bf + (size_t)r1 * CD + c) = packbf(v10 * bscale, v11 * bscale);
            }
        }
    }
}

__global__ __launch_bounds__(256, 2) void k_tgemm(
    const __nv_bfloat16* __restrict__ Ah, const __nv_bfloat16* __restrict__ Al,
    const __nv_bfloat16* __restrict__ Wh, const __nv_bfloat16* __restrict__ Wl,
    const float* __restrict__ bias, float* __restrict__ out,
    __nv_bfloat16* __restrict__ out_bf, float bscale, int npasses)
{
    extern __shared__ char smg[];
    tgemm_body(Ah, Al, Wh, Wl, bias, out, out_bf, bscale, npasses, smg);
}

__global__ __launch_bounds__(256, 2) void k_tgemmKV(
    const __nv_bfloat16* __restrict__ Ah, const __nv_bfloat16* __restrict__ Al,
    const float* __restrict__ bk, const float* __restrict__ bv,
    float* __restrict__ oK, float* __restrict__ oV)
{
    extern __shared__ char smg[];
    int z = blockIdx.z;
    const __nv_bfloat16* Wh = &g_WtH[z + 1][0];
    const __nv_bfloat16* Wl = &g_WtL[z + 1][0];
    const float* bias = (z == 0) ? bk : bv;
    float* out = (z == 0) ? oK : oV;
    tgemm_body(Ah, Al, Wh, Wl, bias, out, nullptr, 1.0f, 3, smg);
}

// ---------------- Xeh (bf16) -> XeT bf16 transpose ----------------
__global__ __launch_bounds__(256) void k_xet() {
    __shared__ __nv_bfloat16 t[32][33];
    int e0 = blockIdx.x * 32, c0 = blockIdx.y * 32;
    int x = threadIdx.x & 31, y = threadIdx.x >> 5;
#pragma unroll
    for (int i = 0; i < 32; i += 8)
        t[y + i][x] = g_Xeh[(size_t)(e0 + y + i) * CD + c0 + x];
    __syncthreads();
#pragma unroll
    for (int i = 0; i < 32; i += 8)
        g_XeT[(size_t)(c0 + y + i) * NE + e0 + x] = t[x][y + i];
}

// ---------------- per-node head attention ----------------
__global__ __launch_bounds__(256) void k_node_attn() {
    __shared__ float sQ[8][256], sK[8][256], sV[8][256], sP[8][64];
    int w = threadIdx.x >> 5, lane = threadIdx.x & 31;
    int node = blockIdx.x * 8 + w;
    const float* qrow = g_Q + (size_t)node * CD;
    const float* krow = g_K + (size_t)node * CD;
    const float* vrow = g_V + (size_t)node * CD;
#pragma unroll
    for (int i = 0; i < 8; i++) {
        int idx = i * 32 + lane;
        sQ[w][idx] = qrow[idx];
        sK[w][idx] = krow[idx];
        sV[w][idx] = vrow[idx];
    }
    __syncwarp();
    int h1 = lane >> 3, gg = lane & 7;
    const float* qp1 = &sQ[w][h1 * 32];
    const float* qp2 = &sQ[w][(h1 + 4) * 32];
    const float* kp  = &sK[w][gg * 32];
    float s1 = 0.f, s2 = 0.f;
#pragma unroll
    for (int d = 0; d < 32; d++) {
        float kv = kp[d];
        s1 += qp1[d] * kv;
        s2 += qp2[d] * kv;
    }
    s1 *= ATT_SCALE; s2 *= ATT_SCALE;
    float m1 = s1, m2 = s2;
#pragma unroll
    for (int off = 4; off >= 1; off >>= 1) {
        m1 = fmaxf(m1, __shfl_xor_sync(0xffffffff, m1, off));
        m2 = fmaxf(m2, __shfl_xor_sync(0xffffffff, m2, off));
    }
    float p1 = __expf(s1 - m1), p2 = __expf(s2 - m2);
    float l1 = p1, l2 = p2;
#pragma unroll
    for (int off = 4; off >= 1; off >>= 1) {
        l1 += __shfl_xor_sync(0xffffffff, l1, off);
        l2 += __shfl_xor_sync(0xffffffff, l2, off);
    }
    sP[w][h1 * 8 + gg] = p1 / l1;
    sP[w][(h1 + 4) * 8 + gg] = p2 / l2;
    __syncwarp();
    float* outp = g_Xnode + (size_t)node * CD;
#pragma unroll
    for (int h = 0; h < 8; h++) {
        float acc = 0.f;
#pragma unroll
        for (int g2 = 0; g2 < 8; g2++) acc += sP[w][h * 8 + g2] * sV[w][g2 * 32 + lane];
        outp[h * 32 + lane] = acc;
    }
}

// ---------------- final: out = relu(Oacc + Xnode) ----------------
__global__ __launch_bounds__(256) void k_final(float* __restrict__ out) {
    int i = blockIdx.x * 256 + threadIdx.x;
    float4 a = ((const float4*)g_Oacc)[i];
    float4 b = ((const float4*)g_Xnode)[i];
    float4 r;
    r.x = fmaxf(a.x + b.x, 0.0f);
    r.y = fmaxf(a.y + b.y, 0.0f);
    r.z = fmaxf(a.z + b.z, 0.0f);
    r.w = fmaxf(a.w + b.w, 0.0f);
    ((float4*)out)[i] = r;
}

// ================== HMMA edge attention v3: warp-pair specialization ==================
// 8 warps as (wm 0..3 = 32-row band, wn 0..1).
// S phase: warp tile 32 rows x 32 edges (Ke duplication 8x -> 4x).
// P halves exchanged via smem with 64-thread named barriers (pair-local, no CTA convoy).
// O phase: warp tile 32 rows x 128 cols, k=64, A from P smem (XeT duplication 8x -> 4x).
#define QLD 264
#define XLD 72
#define PLD 72
#define SM_Q 0
#define KBUF 33792
#define SM_K 67584
#define XBUF 36864
#define SM_X (SM_K + 2 * KBUF)          /* 135168 */
#define SM_P (SM_X + 2 * XBUF)          /* 208896; 128*72*2 = 18432 */
#define SM_L (SM_P + 18432)             /* 227328; 2*128*4 = 1024 */
#define SMEM_EDGE (SM_L + 1024)         /* 228352 */

extern __shared__ char sm_raw[];

__global__ __launch_bounds__(256, 1) void k_edge_attn() {
    const int tid = threadIdx.x;
    const int wid = tid >> 5;
    const int lane = tid & 31;
    const int wm = wid >> 1, wn = wid & 1;
    const int wr = wm * 32;                 // warp row band
    const int en0 = wn * 32;                // S-phase edge half
    const int co0 = wn * 128;               // O-phase column half
    const int row0 = blockIdx.x * 128;
    const uint32_t sb = smem_u32(sm_raw);
    const uint32_t sQ = sb + SM_Q;
    const uint32_t sK = sb + SM_K;
    const uint32_t sX = sb + SM_X;
    const uint32_t sP = sb + SM_P;
    float* lsum = (float*)(sm_raw + SM_L);

    // ---- prologue loads ----
    {
        const char* qg = (const char*)(g_Qb + (size_t)row0 * CD);
#pragma unroll
        for (int j = 0; j < 16; j++) {
            int i = tid + j * 256;
            int r = i >> 5, c8 = i & 31;
            CP16(sQ + (r * QLD + c8 * 8) * 2, qg + (r * 256 + c8 * 8) * 2);
        }
        const char* kg = (const char*)g_Keb;
#pragma unroll
        for (int j = 0; j < 8; j++) {
            int i = tid + j * 256;
            int r = i >> 5, c8 = i & 31;
            CP16(sK + (r * QLD + c8 * 8) * 2, kg + (r * 256 + c8 * 8) * 2);
        }
        const char* xg = (const char*)g_XeT;
#pragma unroll
        for (int j = 0; j < 8; j++) {
            int i = tid + j * 256;
            int c = i >> 3, e8 = i & 7;
            CP16(sX + (c * XLD + e8 * 8) * 2, xg + ((size_t)c * NE + e8 * 8) * 2);
        }
        CP_COMMIT();
    }

    float o[2][16][4];
#pragma unroll
    for (int mt = 0; mt < 2; mt++)
#pragma unroll
        for (int j = 0; j < 16; j++)
#pragma unroll
            for (int q = 0; q < 4; q++) o[mt][j][q] = 0.0f;
    float l_acc[4] = {0.f, 0.f, 0.f, 0.f};

    const int a_row = lane & 15;
    const int a_koff = (lane >> 4) * 8;
    const int b_row = (lane & 7) + (lane >> 4) * 8;
    const int b_koff = ((lane >> 3) & 1) * 8;
    const int qrow = lane >> 2;
    const int qc = 2 * (lane & 3);
    const int barid = 1 + wm;

    for (int t = 0; t < 128; t++) {
        const uint32_t kb = sK + (t & 1) * KBUF;
        const uint32_t xb = sX + (t & 1) * XBUF;
        CP_WAIT0();
        __syncthreads();

        // prefetch next tile
        if (t + 1 < 128) {
            const int nb = (t + 1) & 1;
            const int e0 = (t + 1) * 64;
            const char* kg = (const char*)(g_Keb + (size_t)e0 * CD);
#pragma unroll
            for (int j = 0; j < 8; j++) {
                int i = tid + j * 256;
                int r = i >> 5, c8 = i & 31;
                CP16(sK + nb * KBUF + (r * QLD + c8 * 8) * 2, kg + (r * 256 + c8 * 8) * 2);
            }
            const char* xg = (const char*)g_XeT;
#pragma unroll
            for (int j = 0; j < 8; j++) {
                int i = tid + j * 256;
                int c = i >> 3, e8 = i & 7;
                CP16(sX + nb * XBUF + (c * XLD + e8 * 8) * 2,
                     xg + ((size_t)c * NE + e0 + e8 * 8) * 2);
            }
            CP_COMMIT();
        }

        // ---- S = Q @ Ke^T : warp tile 32 rows x 32 edges ----
        float s[2][4][4];
#pragma unroll
        for (int mt = 0; mt < 2; mt++)
#pragma unroll
            for (int nf = 0; nf < 4; nf++)
#pragma unroll
                for (int q = 0; q < 4; q++) s[mt][nf][q] = 0.0f;

#pragma unroll
        for (int kk = 0; kk < 16; kk++) {
            uint32_t a[2][4];
#pragma unroll
            for (int mt = 0; mt < 2; mt++)
                LDSM4(a[mt][0], a[mt][1], a[mt][2], a[mt][3],
                      sQ + ((wr + mt * 16 + a_row) * QLD + kk * 16 + a_koff) * 2);
#pragma unroll
            for (int gg = 0; gg < 2; gg++) {
                uint32_t b0, b1, b2, b3;
                LDSM4(b0, b1, b2, b3,
                      kb + ((en0 + gg * 16 + b_row) * QLD + kk * 16 + b_koff) * 2);
#pragma unroll
                for (int mt = 0; mt < 2; mt++) {
                    MMA16816(s[mt][gg * 2],     a[mt][0], a[mt][1], a[mt][2], a[mt][3], b0, b1);
                    MMA16816(s[mt][gg * 2 + 1], a[mt][0], a[mt][1], a[mt][2], a[mt][3], b2, b3);
                }
            }
        }

        // ---- P = exp2(S) -> bf16 P smem; partial row sums ----
        float rs[4] = {0.f, 0.f, 0.f, 0.f};
#pragma unroll
        for (int mt = 0; mt < 2; mt++) {
            const int r0 = wr + mt * 16 + qrow;
#pragma unroll
            for (int nf = 0; nf < 4; nf++) {
                float e0f = __bfloat162float(__float2bfloat16(ex2f(s[mt][nf][0])));
                float e1f = __bfloat162float(__float2bfloat16(ex2f(s[mt][nf][1])));
                float e2f = __bfloat162float(__float2bfloat16(ex2f(s[mt][nf][2])));
                float e3f = __bfloat162float(__float2bfloat16(ex2f(s[mt][nf][3])));
                rs[mt * 2]     += e0f + e1f;
                rs[mt * 2 + 1] += e2f + e3f;
                const int c = en0 + nf * 8 + qc;
                *(uint32_t*)(sm_raw + SM_P + (r0 * PLD + c) * 2)       = packbf(e0f, e1f);
                *(uint32_t*)(sm_raw + SM_P + ((r0 + 8) * PLD + c) * 2) = packbf(e2f, e3f);
            }
        }
#pragma unroll
        for (int q = 0; q < 4; q++) {
            rs[q] += __shfl_xor_sync(0xffffffff, rs[q], 1);
            rs[q] += __shfl_xor_sync(0xffffffff, rs[q], 2);
        }
        if ((lane & 3) == 0) {
#pragma unroll
            for (int mt = 0; mt < 2; mt++) {
                const int r0 = wr + mt * 16 + qrow;
                lsum[wn * 128 + r0]     = rs[mt * 2];
                lsum[wn * 128 + r0 + 8] = rs[mt * 2 + 1];
            }
        }
        BAR64(barid);

        // combine row sums (own + partner half)
#pragma unroll
        for (int mt = 0; mt < 2; mt++) {
            const int r0 = wr + mt * 16 + qrow;
            l_acc[mt * 2]     += rs[mt * 2]     + lsum[(wn ^ 1) * 128 + r0];
            l_acc[mt * 2 + 1] += rs[mt * 2 + 1] + lsum[(wn ^ 1) * 128 + r0 + 8];
        }

        // ---- O += P @ XeT : warp tile 32 rows x 128 cols, k = 64 ----
#pragma unroll
        for (int kc = 0; kc < 4; kc++) {
            uint32_t a[2][4];
#pragma unroll
            for (int mt = 0; mt < 2; mt++)
                LDSM4(a[mt][0], a[mt][1], a[mt][2], a[mt][3],
                      sP + ((wr + mt * 16 + a_row) * PLD + kc * 16 + a_koff) * 2);
#pragma unroll
            for (int g2 = 0; g2 < 8; g2++) {
                uint32_t b0, b1, b2, b3;
                LDSM4(b0, b1, b2, b3,
                      xb + ((co0 + g2 * 16 + b_row) * XLD + kc * 16 + b_koff) * 2);
#pragma unroll
                for (int mt = 0; mt < 2; mt++) {
                    MMA16816(o[mt][g2 * 2],     a[mt][0], a[mt][1], a[mt][2], a[mt][3], b0, b1);
                    MMA16816(o[mt][g2 * 2 + 1], a[mt][0], a[mt][1], a[mt][2], a[mt][3], b2, b3);
                }
            }
        }
        BAR64(barid);   // partner done reading P before next tile overwrites
    }

    // ---- epilogue: normalize, write g_Oacc ----
#pragma unroll
    for (int mt = 0; mt < 2; mt++) {
        const int r0 = wr + mt * 16 + qrow;
        const int r1 = r0 + 8;
        const float inv0 = 1.0f / l_acc[mt * 2];
        const float inv1 = 1.0f / l_acc[mt * 2 + 1];
        float* op0 = g_Oacc + (size_t)(row0 + r0) * CD;
        float* op1 = g_Oacc + (size_t)(row0 + r1) * CD;
#pragma unroll
        for (int j = 0; j < 16; j++) {
            const int col = co0 + j * 8 + qc;
            *(float2*)(op0 + col) = make_float2(o[mt][j][0] * inv0, o[mt][j][1] * inv0);
            *(float2*)(op1 + col) = make_float2(o[mt][j][2] * inv1, o[mt][j][3] * inv1);
        }
    }
}

// ---------------- launcher (priority-scheduled stream-forked graph) ----------------
extern "C" void kernel_launch(void* const* d_in, const int* in_sizes, int n_in,
                              void* d_out, int out_size) {
    (void)in_sizes; (void)n_in; (void)out_size;
    const float* X   = (const float*)d_in[0];
    const int* v_ids = (const int*)d_in[1];
    const int* e_ids = (const int*)d_in[2];
    const float* Wq  = (const float*)d_in[3];
    const float* bq  = (const float*)d_in[4];
    const float* Wk  = (const float*)d_in[5];
    const float* bk  = (const float*)d_in[6];
    const float* Wv  = (const float*)d_in[7];
    const float* bv  = (const float*)d_in[8];
    const float* Wke = (const float*)d_in[9];
    const float* bke = (const float*)d_in[10];
    float* out = (float*)d_out;

    float *pQ, *pK, *pV;
    __nv_bfloat16 *pQb, *pKeb, *pXh, *pXl, *pXeh, *pWtH, *pWtL;
    cudaGetSymbolAddress((void**)&pQ,  g_Q);
    cudaGetSymbolAddress((void**)&pK,  g_K);
    cudaGetSymbolAddress((void**)&pV,  g_V);
    cudaGetSymbolAddress((void**)&pQb, g_Qb);
    cudaGetSymbolAddress((void**)&pKeb, g_Keb);
    cudaGetSymbolAddress((void**)&pXh, g_Xh);
    cudaGetSymbolAddress((void**)&pXl, g_Xl);
    cudaGetSymbolAddress((void**)&pXeh, g_Xeh);
    cudaGetSymbolAddress((void**)&pWtH, g_WtH);
    cudaGetSymbolAddress((void**)&pWtL, g_WtL);

    static cudaStream_t s1 = nullptr, s2 = nullptr, s3 = nullptr;
    static cudaEvent_t ef = nullptr, ea = nullptr, eq = nullptr, eb = nullptr, ee = nullptr;
    if (!s1) {
        int loPri, hiPri;
        cudaDeviceGetStreamPriorityRange(&loPri, &hiPri);
        cudaStreamCreateWithPriority(&s1, cudaStreamNonBlocking, hiPri);
        cudaStreamCreateWithPriority(&s3, cudaStreamNonBlocking, hiPri);
        cudaStreamCreateWithPriority(&s2, cudaStreamNonBlocking, loPri);
        cudaEventCreateWithFlags(&ef, cudaEventDisableTiming);
        cudaEventCreateWithFlags(&ea, cudaEventDisableTiming);
        cudaEventCreateWithFlags(&eq, cudaEventDisableTiming);
        cudaEventCreateWithFlags(&eb, cudaEventDisableTiming);
        cudaEventCreateWithFlags(&ee, cudaEventDisableTiming);
        cudaFuncSetAttribute(k_tgemm, cudaFuncAttributeMaxDynamicSharedMemorySize, SMEM_GEMM);
        cudaFuncSetAttribute(k_tgemmKV, cudaFuncAttributeMaxDynamicSharedMemorySize, SMEM_GEMM);
        cudaFuncSetAttribute(k_edge_attn, cudaFuncAttributeMaxDynamicSharedMemorySize, SMEM_EDGE);
    }

    // fork
    cudaEventRecord(ef, 0);
    cudaStreamWaitEvent(s1, ef, 0);
    cudaStreamWaitEvent(s3, ef, 0);

    // --- chain A (s1, HIGH): CSR -> Xe mean -> Wke split -> Ke GEMM -> XeT ---
    k_zi<<<NE / 256, 256, 0, s1>>>();
    k_hist<<<NNZP / 256, 256, 0, s1>>>(e_ids);
    k_scan<<<1, 1024, 0, s1>>>();
    k_fill<<<NNZP / 256, 256, 0, s1>>>(v_ids, e_ids);
    k_gather<<<NE, 256, 0, s1>>>(X);
    k_split_w<<<dim3(8, 8), 256, 0, s1>>>(Wke, pWtH + 3 * CD * CD, pWtL + 3 * CD * CD);
    k_tgemm<<<dim3(NE / 128, 4), 256, SMEM_GEMM, s1>>>(pXeh, nullptr,
                                                       pWtH + 3 * CD * CD, pWtL + 3 * CD * CD,
                                                       bke, nullptr, pKeb, 1.0f, 1);
    k_xet<<<dim3(NE / 32, CD / 32), 256, 0, s1>>>();
    cudaEventRecord(ea, s1);

    // --- chain B (s3, HIGH): X split -> weight split -> Q GEMM -> edge attention ---
    k_split<<<NN * CD / 1024, 256, 0, s3>>>(X, pXh, pXl);
    k_split_w3<<<dim3(8, 8, 3), 256, 0, s3>>>(Wq, Wk, Wv, pWtH, pWtL);
    k_tgemm<<<dim3(NN / 128, 4), 256, SMEM_GEMM, s3>>>(pXh, pXl, pWtH, pWtL,
                                                       bq, pQ, pQb, ATT_SCALE * LOG2E, 3);
    cudaEventRecord(eq, s3);
    cudaStreamWaitEvent(s3, ea, 0);
    k_edge_attn<<<NN / 128, 256, SMEM_EDGE, s3>>>();
    cudaEventRecord(ee, s3);

    // --- overlap work (s2, LOW): KV GEMM -> node attention ---
    cudaStreamWaitEvent(s2, eq, 0);
    k_tgemmKV<<<dim3(NN / 128, 4, 2), 256, SMEM_GEMM, s2>>>(pXh, pXl, bk, bv, pK, pV);
    k_node_attn<<<NN / 8, 256, 0, s2>>>();
    cudaEventRecord(eb, s2);

    // join -> final
    cudaStreamWaitEvent(0, ee, 0);
    cudaStreamWaitEvent(0, eb, 0);
    k_final<<<NN * CD / 1024, 256, 0, 0>>>(out);
}

// round 15
// speedup vs baseline: 1.0799x; 1.0799x over previous
#include <cuda_runtime.h>
#include <cuda_bf16.h>
#include <math.h>
#include <stdint.h>

#define NN   16384
#define NE   8192
#define CD   256
#define NNZP 262144
#define ATT_SCALE 0.17677669529663687f  /* 1/sqrt(32) */
#define LOG2E 1.4426950408889634f

// ---------------- scratch (device globals; no allocation allowed) ----------------
__device__ float g_Q[NN * CD];
__device__ float g_K[NN * CD];
__device__ float g_V[NN * CD];
__device__ float g_Xnode[NN * CD];
__device__ float g_Oacc[NN * CD];
__device__ __nv_bfloat16 g_Qb[NN * CD];
__device__ __nv_bfloat16 g_Keb[NE * CD];
__device__ __nv_bfloat16 g_XeT[CD * NE];
__device__ __nv_bfloat16 g_Xh[NN * CD];
__device__ __nv_bfloat16 g_Xl[NN * CD];
__device__ __nv_bfloat16 g_Xeh[NE * CD];
__device__ __nv_bfloat16 g_WtH[4][CD * CD];
__device__ __nv_bfloat16 g_WtL[4][CD * CD];
__device__ int g_hist[NE];
__device__ int g_off[NE + 1];
__device__ int g_cur[NE];
__device__ int g_idx[NNZP];

// ================= PTX helpers =================
__device__ __forceinline__ uint32_t smem_u32(const void* p) {
    uint32_t a;
    asm("{ .reg .u64 t; cvta.to.shared.u64 t, %1; cvt.u32.u64 %0, t; }" : "=r"(a) : "l"(p));
    return a;
}
#define CP16(dst, src)   asm volatile("cp.async.cg.shared.global [%0], [%1], 16;" :: "r"(dst), "l"(src) : "memory")
#define CP_COMMIT()      asm volatile("cp.async.commit_group;" ::: "memory")
#define CP_WAIT0()       asm volatile("cp.async.wait_group 0;" ::: "memory")
#define CP_WAIT1()       asm volatile("cp.async.wait_group 1;" ::: "memory")

#define LDSM4(r0, r1, r2, r3, addr) \
    asm volatile("ldmatrix.sync.aligned.m8n8.x4.shared.b16 {%0,%1,%2,%3}, [%4];" \
                 : "=r"(r0), "=r"(r1), "=r"(r2), "=r"(r3) : "r"(addr))

#define MMA16816(d, a0, a1, a2, a3, b0, b1) \
    asm volatile("mma.sync.aligned.m16n8k16.row.col.f32.bf16.bf16.f32 " \
                 "{%0,%1,%2,%3}, {%4,%5,%6,%7}, {%8,%9}, {%0,%1,%2,%3};" \
                 : "+f"((d)[0]), "+f"((d)[1]), "+f"((d)[2]), "+f"((d)[3]) \
                 : "r"(a0), "r"(a1), "r"(a2), "r"(a3), "r"(b0), "r"(b1))

__device__ __forceinline__ uint32_t packbf(float x, float y) {
    __nv_bfloat162 h = __float22bfloat162_rn(make_float2(x, y));
    return *(uint32_t*)&h;
}
__device__ __forceinline__ float ex2f(float x) {
    float y;
    asm("ex2.approx.ftz.f32 %0, %1;" : "=f"(y) : "f"(x));
    return y;
}

// ================= CSR build + gather aggregation =================
__global__ __launch_bounds__(256) void k_zi() {
    int i = blockIdx.x * 256 + threadIdx.x;
    g_hist[i] = 0;
}
__global__ __launch_bounds__(256) void k_hist(const int* __restrict__ e_ids) {
    int i = blockIdx.x * 256 + threadIdx.x;
    atomicAdd(&g_hist[e_ids[i]], 1);
}
__global__ __launch_bounds__(1024) void k_scan() {
    __shared__ int ws[32];
    int tid = threadIdx.x;
    int lane = tid & 31, w = tid >> 5;
    int base = tid * 8;
    int v[8];
    int s = 0;
#pragma unroll
    for (int i = 0; i < 8; i++) { v[i] = g_hist[base + i]; s += v[i]; }
    int pre = s;
#pragma unroll
    for (int off = 1; off < 32; off <<= 1) {
        int n = __shfl_up_sync(0xffffffff, pre, off);
        if (lane >= off) pre += n;
    }
    if (lane == 31) ws[w] = pre;
    __syncthreads();
    if (w == 0) {
        int t = ws[lane];
#pragma unroll
        for (int off = 1; off < 32; off <<= 1) {
            int n = __shfl_up_sync(0xffffffff, t, off);
            if (lane >= off) t += n;
        }
        ws[lane] = t;
    }
    __syncthreads();
    int excl = (w > 0 ? ws[w - 1] : 0) + (pre - s);
#pragma unroll
    for (int i = 0; i < 8; i++) {
        g_off[base + i] = excl;
        g_cur[base + i] = excl;
        excl += v[i];
    }
    if (tid == 1023) g_off[NE] = NNZP;
}
__global__ __launch_bounds__(256) void k_fill(const int* __restrict__ v_ids,
                                              const int* __restrict__ e_ids) {
    int i = blockIdx.x * 256 + threadIdx.x;
    int e = e_ids[i];
    int pos = atomicAdd(&g_cur[e], 1);
    g_idx[pos] = v_ids[i];
}
// one block per edge: 4 vertices in flight (float4 per thread), smem combine, mean, bf16
__global__ __launch_bounds__(256) void k_gather(const float* __restrict__ X) {
    __shared__ float4 sm[256];
    int e = blockIdx.x;
    int tid = threadIdx.x;
    int q = tid >> 6;              // vertex slot 0..3
    int c4 = (tid & 63) << 2;      // channel quad
    int j0 = g_off[e], j1 = g_off[e + 1];
    float4 acc = make_float4(0.f, 0.f, 0.f, 0.f);
    for (int j = j0 + q; j < j1; j += 4) {
        int v = __ldg(&g_idx[j]);
        float4 x = *(const float4*)(X + (size_t)v * CD + c4);
        acc.x += x.x; acc.y += x.y; acc.z += x.z; acc.w += x.w;
    }
    sm[tid] = acc;
    __syncthreads();
    if (q == 0) {
        float4 a0 = sm[tid], a1 = sm[tid + 64], a2 = sm[tid + 128], a3 = sm[tid + 192];
        float inv = 1.0f / fmaxf((float)(j1 - j0), 1.0f);
        float m0 = (a0.x + a1.x + a2.x + a3.x) * inv;
        float m1 = (a0.y + a1.y + a2.y + a3.y) * inv;
        float m2 = (a0.z + a1.z + a2.z + a3.z) * inv;
        float m3 = (a0.w + a1.w + a2.w + a3.w) * inv;
        uint32_t* dst = (uint32_t*)(g_Xeh + (size_t)e * CD + c4);
        dst[0] = packbf(m0, m1);
        dst[1] = packbf(m2, m3);
    }
}

// ---------------- fp32 -> bf16 hi/lo split ----------------
__global__ __launch_bounds__(256) void k_split(const float* __restrict__ in,
                                               __nv_bfloat16* __restrict__ hi,
                                               __nv_bfloat16* __restrict__ lo) {
    int i = blockIdx.x * 256 + threadIdx.x;
    float4 v = ((const float4*)in)[i];
    __nv_bfloat16 h0 = __float2bfloat16(v.x), h1 = __float2bfloat16(v.y);
    __nv_bfloat16 h2 = __float2bfloat16(v.z), h3 = __float2bfloat16(v.w);
    uint32_t* hp = (uint32_t*)hi;
    uint32_t* lp = (uint32_t*)lo;
    hp[2 * i]     = packbf(__bfloat162float(h0), __bfloat162float(h1));
    hp[2 * i + 1] = packbf(__bfloat162float(h2), __bfloat162float(h3));
    lp[2 * i]     = packbf(v.x - __bfloat162float(h0), v.y - __bfloat162float(h1));
    lp[2 * i + 1] = packbf(v.z - __bfloat162float(h2), v.w - __bfloat162float(h3));
}

// ---------------- W [k][n] -> Wt hi/lo [n][k] bf16 ----------------
__device__ __forceinline__ void split_w_body(const float* __restrict__ W,
                                             __nv_bfloat16* __restrict__ WtH,
                                             __nv_bfloat16* __restrict__ WtL) {
    __shared__ float t[32][33];
    int k0 = blockIdx.x * 32, n0 = blockIdx.y * 32;
    int x = threadIdx.x & 31, y = threadIdx.x >> 5;
#pragma unroll
    for (int i = 0; i < 32; i += 8)
        t[y + i][x] = W[(size_t)(k0 + y + i) * CD + n0 + x];
    __syncthreads();
#pragma unroll
    for (int i = 0; i < 32; i += 8) {
        float w = t[x][y + i];
        __nv_bfloat16 h = __float2bfloat16(w);
        WtH[(size_t)(n0 + y + i) * CD + k0 + x] = h;
        WtL[(size_t)(n0 + y + i) * CD + k0 + x] = __float2bfloat16(w - __bfloat162float(h));
    }
}
__global__ __launch_bounds__(256) void k_split_w(const float* __restrict__ W,
                                                 __nv_bfloat16* __restrict__ WtH,
                                                 __nv_bfloat16* __restrict__ WtL) {
    split_w_body(W, WtH, WtL);
}
__global__ __launch_bounds__(256) void k_split_w3(const float* __restrict__ W0,
                                                  const float* __restrict__ W1,
                                                  const float* __restrict__ W2,
                                                  __nv_bfloat16* __restrict__ WtH,
                                                  __nv_bfloat16* __restrict__ WtL) {
    int z = blockIdx.z;
    const float* W = (z == 0) ? W0 : (z == 1) ? W1 : W2;
    split_w_body(W, WtH + (size_t)z * CD * CD, WtL + (size_t)z * CD * CD);
}

// ================== split-bf16 tensor-core GEMM ==================
#define GLD 72
#define G_AH 0
#define G_AL 18432
#define G_WH 36864
#define G_WL 46080
#define G_STAGE 55296
#define SMEM_GEMM 110592

__device__ __forceinline__ void tgemm_body(
    const __nv_bfloat16* __restrict__ Ah, const __nv_bfloat16* __restrict__ Al,
    const __nv_bfloat16* __restrict__ Wh, const __nv_bfloat16* __restrict__ Wl,
    const float* __restrict__ bias, float* __restrict__ out,
    __nv_bfloat16* __restrict__ out_bf, float bscale, int npasses, char* smg)
{
    const uint32_t sb = smem_u32(smg);
    const int tid = threadIdx.x, wid = tid >> 5, lane = tid & 31;
    const int row0 = blockIdx.x * 128, col0 = blockIdx.y * 64;
    const int wm = wid >> 1, wn = wid & 1;

    const int a_row = lane & 15;
    const int a_koff = (lane >> 4) * 8;
    const int b_row = (lane & 7) + (lane >> 4) * 8;
    const int b_koff = ((lane >> 3) & 1) * 8;

    float acc[2][4][4];
#pragma unroll
    for (int im = 0; im < 2; im++)
#pragma unroll
        for (int nf = 0; nf < 4; nf++)
#pragma unroll
            for (int q = 0; q < 4; q++) acc[im][nf][q] = 0.0f;

    auto load_stage = [&](int kc, int st) {
        uint32_t base = sb + st * G_STAGE;
        const char* ah = (const char*)(Ah + (size_t)row0 * CD + kc * 64);
#pragma unroll
        for (int j = 0; j < 4; j++) {
            int i = tid + j * 256;
            int r = i >> 3, c8 = i & 7;
            CP16(base + G_AH + (r * GLD + c8 * 8) * 2, ah + (r * CD + c8 * 8) * 2);
        }
        const char* wh = (const char*)(Wh + (size_t)col0 * CD + kc * 64);
#pragma unroll
        for (int j = 0; j < 2; j++) {
            int i = tid + j * 256;
            int r = i >> 3, c8 = i & 7;
            CP16(base + G_WH + (r * GLD + c8 * 8) * 2, wh + (r * CD + c8 * 8) * 2);
        }
        if (npasses == 3) {
            const char* al = (const char*)(Al + (size_t)row0 * CD + kc * 64);
#pragma unroll
            for (int j = 0; j < 4; j++) {
                int i = tid + j * 256;
                int r = i >> 3, c8 = i & 7;
                CP16(base + G_AL + (r * GLD + c8 * 8) * 2, al + (r * CD + c8 * 8) * 2);
            }
            const char* wl = (const char*)(Wl + (size_t)col0 * CD + kc * 64);
#pragma unroll
            for (int j = 0; j < 2; j++) {
                int i = tid + j * 256;
                int r = i >> 3, c8 = i & 7;
                CP16(base + G_WL + (r * GLD + c8 * 8) * 2, wl + (r * CD + c8 * 8) * 2);
            }
        }
    };

    load_stage(0, 0);
    CP_COMMIT();

    for (int kc = 0; kc < 4; kc++) {
        if (kc < 3) {
            load_stage(kc + 1, (kc + 1) & 1);
            CP_COMMIT();
            CP_WAIT1();
        } else {
            CP_WAIT0();
        }
        __syncthreads();

        const uint32_t base = sb + (kc & 1) * G_STAGE;
        const uint32_t aoffs[3] = {G_AH, G_AH, G_AL};
        const uint32_t woffs[3] = {G_WH, G_WL, G_WH};
        for (int p = 0; p < npasses; p++) {
            const uint32_t ab = base + aoffs[p];
            const uint32_t wb = base + woffs[p];
#pragma unroll
            for (int kk = 0; kk < 4; kk++) {
                uint32_t a[2][4];
#pragma unroll
                for (int im = 0; im < 2; im++)
                    LDSM4(a[im][0], a[im][1], a[im][2], a[im][3],
                          ab + ((wm * 32 + im * 16 + a_row) * GLD + kk * 16 + a_koff) * 2);
#pragma unroll
                for (int gn = 0; gn < 2; gn++) {
                    uint32_t b0, b1, b2, b3;
                    LDSM4(b0, b1, b2, b3,
                          wb + ((wn * 32 + gn * 16 + b_row) * GLD + kk * 16 + b_koff) * 2);
#pragma unroll
                    for (int im = 0; im < 2; im++) {
                        MMA16816(acc[im][gn * 2],     a[im][0], a[im][1], a[im][2], a[im][3], b0, b1);
                        MMA16816(acc[im][gn * 2 + 1], a[im][0], a[im][1], a[im][2], a[im][3], b2, b3);
                    }
                }
            }
        }
        __syncthreads();
    }

    const int r_base = row0 + wm * 32 + (lane >> 2);
    const int c_base = col0 + wn * 32 + 2 * (lane & 3);
#pragma unroll
    for (int im = 0; im < 2; im++) {
        const int r0 = r_base + im * 16;
        const int r1 = r0 + 8;
#pragma unroll
        for (int nf = 0; nf < 4; nf++) {
            const int c = c_base + nf * 8;
            const float bv0 = __ldg(bias + c), bv1 = __ldg(bias + c + 1);
            float v00 = acc[im][nf][0] + bv0, v01 = acc[im][nf][1] + bv1;
            float v10 = acc[im][nf][2] + bv0, v11 = acc[im][nf][3] + bv1;
            if (out) {
                *(float2*)(out + (size_t)r0 * CD + c) = make_float2(v00, v01);
                *(float2*)(out + (size_t)r1 * CD + c) = make_float2(v10, v11);
            }
            if (out_bf) {
                *(uint32_t*)(out_bf + (size_t)r0 * CD + c) = packbf(v00 * bscale, v01 * bscale);
                *(uint32_t*)(out_bf + (size_t)r1 * CD + c) = packbf(v10 * bscale, v11 * bscale);
            }
        }
    }
}

__global__ __launch_bounds__(256, 2) void k_tgemm(
    const __nv_bfloat16* __restrict__ Ah, const __nv_bfloat16* __restrict__ Al,
    const __nv_bfloat16* __restrict__ Wh, const __nv_bfloat16* __restrict__ Wl,
    const float* __restrict__ bias, float* __restrict__ out,
    __nv_bfloat16* __restrict__ out_bf, float bscale, int npasses)
{
    extern __shared__ char smg[];
    tgemm_body(Ah, Al, Wh, Wl, bias, out, out_bf, bscale, npasses, smg);
}

__global__ __launch_bounds__(256, 2) void k_tgemmKV(
    const __nv_bfloat16* __restrict__ Ah, const __nv_bfloat16* __restrict__ Al,
    const float* __restrict__ bk, const float* __restrict__ bv,
    float* __restrict__ oK, float* __restrict__ oV)
{
    extern __shared__ char smg[];
    int z = blockIdx.z;
    const __nv_bfloat16* Wh = &g_WtH[z + 1][0];
    const __nv_bfloat16* Wl = &g_WtL[z + 1][0];
    const float* bias = (z == 0) ? bk : bv;
    float* out = (z == 0) ? oK : oV;
    tgemm_body(Ah, Al, Wh, Wl, bias, out, nullptr, 1.0f, 3, smg);
}

// ---------------- Xeh (bf16) -> XeT bf16 transpose ----------------
__global__ __launch_bounds__(256) void k_xet() {
    __shared__ __nv_bfloat16 t[32][33];
    int e0 = blockIdx.x * 32, c0 = blockIdx.y * 32;
    int x = threadIdx.x & 31, y = threadIdx.x >> 5;
#pragma unroll
    for (int i = 0; i < 32; i += 8)
        t[y + i][x] = g_Xeh[(size_t)(e0 + y + i) * CD + c0 + x];
    __syncthreads();
#pragma unroll
    for (int i = 0; i < 32; i += 8)
        g_XeT[(size_t)(c0 + y + i) * NE + e0 + x] = t[x][y + i];
}

// ---------------- per-node head attention ----------------
__global__ __launch_bounds__(256) void k_node_attn() {
    __shared__ float sQ[8][256], sK[8][256], sV[8][256], sP[8][64];
    int w = threadIdx.x >> 5, lane = threadIdx.x & 31;
    int node = blockIdx.x * 8 + w;
    const float* qrow = g_Q + (size_t)node * CD;
    const float* krow = g_K + (size_t)node * CD;
    const float* vrow = g_V + (size_t)node * CD;
#pragma unroll
    for (int i = 0; i < 8; i++) {
        int idx = i * 32 + lane;
        sQ[w][idx] = qrow[idx];
        sK[w][idx] = krow[idx];
        sV[w][idx] = vrow[idx];
    }
    __syncwarp();
    int h1 = lane >> 3, gg = lane & 7;
    const float* qp1 = &sQ[w][h1 * 32];
    const float* qp2 = &sQ[w][(h1 + 4) * 32];
    const float* kp  = &sK[w][gg * 32];
    float s1 = 0.f, s2 = 0.f;
#pragma unroll
    for (int d = 0; d < 32; d++) {
        float kv = kp[d];
        s1 += qp1[d] * kv;
        s2 += qp2[d] * kv;
    }
    s1 *= ATT_SCALE; s2 *= ATT_SCALE;
    float m1 = s1, m2 = s2;
#pragma unroll
    for (int off = 4; off >= 1; off >>= 1) {
        m1 = fmaxf(m1, __shfl_xor_sync(0xffffffff, m1, off));
        m2 = fmaxf(m2, __shfl_xor_sync(0xffffffff, m2, off));
    }
    float p1 = __expf(s1 - m1), p2 = __expf(s2 - m2);
    float l1 = p1, l2 = p2;
#pragma unroll
    for (int off = 4; off >= 1; off >>= 1) {
        l1 += __shfl_xor_sync(0xffffffff, l1, off);
        l2 += __shfl_xor_sync(0xffffffff, l2, off);
    }
    sP[w][h1 * 8 + gg] = p1 / l1;
    sP[w][(h1 + 4) * 8 + gg] = p2 / l2;
    __syncwarp();
    float* outp = g_Xnode + (size_t)node * CD;
#pragma unroll
    for (int h = 0; h < 8; h++) {
        float acc = 0.f;
#pragma unroll
        for (int g2 = 0; g2 < 8; g2++) acc += sP[w][h * 8 + g2] * sV[w][g2 * 32 + lane];
        outp[h * 32 + lane] = acc;
    }
}

// ---------------- final: out = relu(Oacc + Xnode) ----------------
__global__ __launch_bounds__(256) void k_final(float* __restrict__ out) {
    int i = blockIdx.x * 256 + threadIdx.x;
    float4 a = ((const float4*)g_Oacc)[i];
    float4 b = ((const float4*)g_Xnode)[i];
    float4 r;
    r.x = fmaxf(a.x + b.x, 0.0f);
    r.y = fmaxf(a.y + b.y, 0.0f);
    r.z = fmaxf(a.z + b.z, 0.0f);
    r.w = fmaxf(a.w + b.w, 0.0f);
    ((float4*)out)[i] = r;
}

// ================== HMMA edge attention (R11 single-barrier; writes O/l to g_Oacc) ==================
#define QLD 264
#define XLD 72
#define SM_Q 0
#define KBUF 33792
#define SM_K 67584
#define XBUF 36864
#define SM_X (SM_K + 2 * KBUF)
#define SMEM_EDGE (SM_X + 2 * XBUF)

extern __shared__ char sm_raw[];

__global__ __launch_bounds__(256, 1) void k_edge_attn() {
    const int tid = threadIdx.x;
    const int wid = tid >> 5;
    const int lane = tid & 31;
    const int row0 = blockIdx.x * 128;
    const int wr0 = wid * 16;
    const uint32_t sb = smem_u32(sm_raw);
    const uint32_t sQ = sb + SM_Q;
    const uint32_t sK = sb + SM_K;
    const uint32_t sX = sb + SM_X;

    {
        const char* qg = (const char*)(g_Qb + (size_t)row0 * CD);
#pragma unroll
        for (int j = 0; j < 16; j++) {
            int i = tid + j * 256;
            int r = i >> 5, c8 = i & 31;
            CP16(sQ + (r * QLD + c8 * 8) * 2, qg + (r * 256 + c8 * 8) * 2);
        }
        const char* kg = (const char*)g_Keb;
#pragma unroll
        for (int j = 0; j < 8; j++) {
            int i = tid + j * 256;
            int r = i >> 5, c8 = i & 31;
            CP16(sK + (r * QLD + c8 * 8) * 2, kg + (r * 256 + c8 * 8) * 2);
        }
        const char* xg = (const char*)g_XeT;
#pragma unroll
        for (int j = 0; j < 8; j++) {
            int i = tid + j * 256;
            int c = i >> 3, e8 = i & 7;
            CP16(sX + (c * XLD + e8 * 8) * 2, xg + ((size_t)c * NE + e8 * 8) * 2);
        }
        CP_COMMIT();
    }

    float o[32][4];
#pragma unroll
    for (int j = 0; j < 32; j++)
#pragma unroll
        for (int q = 0; q < 4; q++) o[j][q] = 0.0f;
    float l0 = 0.0f, l1 = 0.0f;

    const int a_row = lane & 15;
    const int a_koff = (lane >> 4) * 8;
    const int b_row = (lane & 7) + (lane >> 4) * 8;
    const int b_koff = ((lane >> 3) & 1) * 8;

    for (int t = 0; t < 128; t++) {
        const uint32_t kb = sK + (t & 1) * KBUF;
        const uint32_t xb = sX + (t & 1) * XBUF;
        CP_WAIT0();
        __syncthreads();

        if (t + 1 < 128) {
            const int nb = (t + 1) & 1;
            const int e0 = (t + 1) * 64;
            const char* kg = (const char*)(g_Keb + (size_t)e0 * CD);
#pragma unroll
            for (int j = 0; j < 8; j++) {
                int i = tid + j * 256;
                int r = i >> 5, c8 = i & 31;
                CP16(sK + nb * KBUF + (r * QLD + c8 * 8) * 2, kg + (r * 256 + c8 * 8) * 2);
            }
            const char* xg = (const char*)g_XeT;
#pragma unroll
            for (int j = 0; j < 8; j++) {
                int i = tid + j * 256;
                int c = i >> 3, e8 = i & 7;
                CP16(sX + nb * XBUF + (c * XLD + e8 * 8) * 2,
                     xg + ((size_t)c * NE + e0 + e8 * 8) * 2);
            }
            CP_COMMIT();
        }

        float s[8][4];
#pragma unroll
        for (int j = 0; j < 8; j++)
#pragma unroll
            for (int q = 0; q < 4; q++) s[j][q] = 0.0f;

#pragma unroll
        for (int kk = 0; kk < 16; kk++) {
            uint32_t a0, a1, a2, a3;
            LDSM4(a0, a1, a2, a3, sQ + ((wr0 + a_row) * QLD + kk * 16 + a_koff) * 2);
#pragma unroll
            for (int g = 0; g < 4; g++) {
                uint32_t b0, b1, b2, b3;
                LDSM4(b0, b1, b2, b3, kb + ((g * 16 + b_row) * QLD + kk * 16 + b_koff) * 2);
                MMA16816(s[2 * g], a0, a1, a2, a3, b0, b1);
                MMA16816(s[2 * g + 1], a0, a1, a2, a3, b2, b3);
            }
        }

        uint32_t pa[4][4];
        float ls0 = 0.0f, ls1 = 0.0f;
#pragma unroll
        for (int j = 0; j < 8; j++) {
            float e0f = __bfloat162float(__float2bfloat16(ex2f(s[j][0])));
            float e1f = __bfloat162float(__float2bfloat16(ex2f(s[j][1])));
            float e2f = __bfloat162float(__float2bfloat16(ex2f(s[j][2])));
            float e3f = __bfloat162float(__float2bfloat16(ex2f(s[j][3])));
            ls0 += e0f + e1f;
            ls1 += e2f + e3f;
            int kc = j >> 1, hi = (j & 1) * 2;
            pa[kc][hi]     = packbf(e0f, e1f);
            pa[kc][hi + 1] = packbf(e2f, e3f);
        }
        ls0 += __shfl_xor_sync(0xffffffff, ls0, 1);
        ls0 += __shfl_xor_sync(0xffffffff, ls0, 2);
        ls1 += __shfl_xor_sync(0xffffffff, ls1, 1);
        ls1 += __shfl_xor_sync(0xffffffff, ls1, 2);
        l0 += ls0;
        l1 += ls1;

#pragma unroll
        for (int kc = 0; kc < 4; kc++) {
#pragma unroll
            for (int g = 0; g < 16; g++) {
                uint32_t b0, b1, b2, b3;
                LDSM4(b0, b1, b2, b3, xb + ((g * 16 + b_row) * XLD + kc * 16 + b_koff) * 2);
                MMA16816(o[2 * g], pa[kc][0], pa[kc][1], pa[kc][2], pa[kc][3], b0, b1);
                MMA16816(o[2 * g + 1], pa[kc][0], pa[kc][1], pa[kc][2], pa[kc][3], b2, b3);
            }
        }
    }

    {
        const int r = wr0 + (lane >> 2);
        const int c0 = 2 * (lane & 3);
        const float inv0 = 1.0f / l0;
        const float inv1 = 1.0f / l1;
        const int g0 = row0 + r;
        const int g1 = g0 + 8;
        float* op0 = g_Oacc + (size_t)g0 * CD;
        float* op1 = g_Oacc + (size_t)g1 * CD;
#pragma unroll
        for (int j = 0; j < 32; j++) {
            int col = j * 8 + c0;
            *(float2*)(op0 + col) = make_float2(o[j][0] * inv0, o[j][1] * inv0);
            *(float2*)(op1 + col) = make_float2(o[j][2] * inv1, o[j][3] * inv1);
        }
    }
}

// ---------------- launcher (3 streams; R14 schedule folded in) ----------------
extern "C" void kernel_launch(void* const* d_in, const int* in_sizes, int n_in,
                              void* d_out, int out_size) {
    (void)in_sizes; (void)n_in; (void)out_size;
    const float* X   = (const float*)d_in[0];
    const int* v_ids = (const int*)d_in[1];
    const int* e_ids = (const int*)d_in[2];
    const float* Wq  = (const float*)d_in[3];
    const float* bq  = (const float*)d_in[4];
    const float* Wk  = (const float*)d_in[5];
    const float* bk  = (const float*)d_in[6];
    const float* Wv  = (const float*)d_in[7];
    const float* bv  = (const float*)d_in[8];
    const float* Wke = (const float*)d_in[9];
    const float* bke = (const float*)d_in[10];
    float* out = (float*)d_out;

    float *pQ, *pK, *pV;
    __nv_bfloat16 *pQb, *pKeb, *pXh, *pXl, *pXeh, *pWtH, *pWtL;
    cudaGetSymbolAddress((void**)&pQ,  g_Q);
    cudaGetSymbolAddress((void**)&pK,  g_K);
    cudaGetSymbolAddress((void**)&pV,  g_V);
    cudaGetSymbolAddress((void**)&pQb, g_Qb);
    cudaGetSymbolAddress((void**)&pKeb, g_Keb);
    cudaGetSymbolAddress((void**)&pXh, g_Xh);
    cudaGetSymbolAddress((void**)&pXl, g_Xl);
    cudaGetSymbolAddress((void**)&pXeh, g_Xeh);
    cudaGetSymbolAddress((void**)&pWtH, g_WtH);
    cudaGetSymbolAddress((void**)&pWtL, g_WtL);

    static cudaStream_t s1 = nullptr, s2 = nullptr, s3 = nullptr;
    static cudaEvent_t ef = nullptr, eg = nullptr, ea = nullptr, ek = nullptr,
                       eq = nullptr, eb = nullptr, ee = nullptr;
    if (!s1) {
        int loPri, hiPri;
        cudaDeviceGetStreamPriorityRange(&loPri, &hiPri);
        cudaStreamCreateWithPriority(&s1, cudaStreamNonBlocking, hiPri);
        cudaStreamCreateWithPriority(&s3, cudaStreamNonBlocking, hiPri);
        cudaStreamCreateWithPriority(&s2, cudaStreamNonBlocking, loPri);
        cudaEventCreateWithFlags(&ef, cudaEventDisableTiming);
        cudaEventCreateWithFlags(&eg, cudaEventDisableTiming);
        cudaEventCreateWithFlags(&ea, cudaEventDisableTiming);
        cudaEventCreateWithFlags(&ek, cudaEventDisableTiming);
        cudaEventCreateWithFlags(&eq, cudaEventDisableTiming);
        cudaEventCreateWithFlags(&eb, cudaEventDisableTiming);
        cudaEventCreateWithFlags(&ee, cudaEventDisableTiming);
        cudaFuncSetAttribute(k_tgemm, cudaFuncAttributeMaxDynamicSharedMemorySize, SMEM_GEMM);
        cudaFuncSetAttribute(k_tgemmKV, cudaFuncAttributeMaxDynamicSharedMemorySize, SMEM_GEMM);
        cudaFuncSetAttribute(k_edge_attn, cudaFuncAttributeMaxDynamicSharedMemorySize, SMEM_EDGE);
    }

    // fork
    cudaEventRecord(ef, 0);
    cudaStreamWaitEvent(s1, ef, 0);
    cudaStreamWaitEvent(s2, ef, 0);
    cudaStreamWaitEvent(s3, ef, 0);

    // --- chain A (s1, HIGH): CSR -> Xe mean -> XeT ---
    k_zi<<<NE / 256, 256, 0, s1>>>();
    k_hist<<<NNZP / 256, 256, 0, s1>>>(e_ids);
    k_scan<<<1, 1024, 0, s1>>>();
    k_fill<<<NNZP / 256, 256, 0, s1>>>(v_ids, e_ids);
    k_gather<<<NE, 256, 0, s1>>>(X);
    cudaEventRecord(eg, s1);
    k_xet<<<dim3(NE / 32, CD / 32), 256, 0, s1>>>();
    cudaEventRecord(ea, s1);

    // --- s2 (LOW): Wke split at fork -> Ke GEMM (after gather, concurrent with xet);
    //     later: KV GEMM -> node attention ---
    k_split_w<<<dim3(8, 8), 256, 0, s2>>>(Wke, pWtH + 3 * CD * CD, pWtL + 3 * CD * CD);
    cudaStreamWaitEvent(s2, eg, 0);
    k_tgemm<<<dim3(NE / 128, 4), 256, SMEM_GEMM, s2>>>(pXeh, nullptr,
                                                       pWtH + 3 * CD * CD, pWtL + 3 * CD * CD,
                                                       bke, nullptr, pKeb, 1.0f, 1);
    cudaEventRecord(ek, s2);

    // --- chain B (s3, HIGH): X split -> weight split -> Q GEMM -> edge attention ---
    k_split<<<NN * CD / 1024, 256, 0, s3>>>(X, pXh, pXl);
    k_split_w3<<<dim3(8, 8, 3), 256, 0, s3>>>(Wq, Wk, Wv, pWtH, pWtL);
    k_tgemm<<<dim3(NN / 128, 4), 256, SMEM_GEMM, s3>>>(pXh, pXl, pWtH, pWtL,
                                                       bq, pQ, pQb, ATT_SCALE * LOG2E, 3);
    cudaEventRecord(eq, s3);
    cudaStreamWaitEvent(s3, ea, 0);
    cudaStreamWaitEvent(s3, ek, 0);
    k_edge_attn<<<NN / 128, 256, SMEM_EDGE, s3>>>();
    cudaEventRecord(ee, s3);

    // --- overlap work (s2, LOW, continues): KV GEMM -> node attention ---
    cudaStreamWaitEvent(s2, eq, 0);
    k_tgemmKV<<<dim3(NN / 128, 4, 2), 256, SMEM_GEMM, s2>>>(pXh, pXl, bk, bv, pK, pV);
    k_node_attn<<<NN / 8, 256, 0, s2>>>();
    cudaEventRecord(eb, s2);

    // join -> final
    cudaStreamWaitEvent(0, ee, 0);
    cudaStreamWaitEvent(0, eb, 0);
    k_final<<<NN * CD / 1024, 256, 0, 0>>>(out);
}